// round 2
// baseline (speedup 1.0000x reference)
#include <cuda_runtime.h>
#include <math_constants.h>
#include <cstdint>

#define Bc    8
#define Np    4096
#define Ms    2048
#define Kn    16
#define CIN   64
#define COUT  128
#define BNr   (Bc*Np)     // 32768 rows
#define BM    (Bc*Ms)     // 16384 sampled points
#define NBLK_GEMM 256

typedef unsigned long long u64;

// packed f32x2 helpers (each half IEEE round-to-nearest => bit-identical to scalar rn)
#define ADDX2(o,a,b) asm("add.rn.f32x2 %0,%1,%2;" : "=l"(o) : "l"(a), "l"(b))
#define MULX2(o,a,b) asm("mul.rn.f32x2 %0,%1,%2;" : "=l"(o) : "l"(a), "l"(b))
__device__ __forceinline__ u64 packx2(float lo, float hi) {
    u64 o; asm("mov.b64 %0,{%1,%2};" : "=l"(o) : "f"(lo), "f"(hi)); return o;
}
__device__ __forceinline__ void unpackx2(float& lo, float& hi, u64 v) {
    asm("mov.b64 {%0,%1},%2;" : "=f"(lo), "=f"(hi) : "l"(v));
}

// ---------------- device scratch ----------------
__device__ float  g_h[BNr*COUT];             // 16 MB: mlp activations
__device__ float  g_part[NBLK_GEMM*COUT*2];  // per-block BN partials
__device__ float  g_scale[COUT];
__device__ float  g_shift[COUT];
__device__ float4 g_pos4[BNr];               // xyz
__device__ u64    g_nx[BNr/2];               // packed (-x) pairs
__device__ u64    g_ny[BNr/2];
__device__ u64    g_nz[BNr/2];
__device__ float4 g_qpos[BM];                // sampled xyz
__device__ int    g_nbr[BM*Kn];              // global row indices of neighbors

// ---------------- prep: positions + packed negated pairs ----------------
__global__ __launch_bounds__(256) void k_prep(const float* __restrict__ pos) {
    int i = blockIdx.x * 256 + threadIdx.x;      // pair index
    if (i >= BNr/2) return;
    const float* p = pos + (size_t)i * 6;
    float x0=p[0], y0=p[1], z0=p[2], x1=p[3], y1=p[4], z1=p[5];
    g_pos4[2*i]   = make_float4(x0, y0, z0, 0.f);
    g_pos4[2*i+1] = make_float4(x1, y1, z1, 0.f);
    g_nx[i] = packx2(-x0, -x1);
    g_ny[i] = packx2(-y0, -y1);
    g_nz[i] = packx2(-z0, -z1);
}

// ---------------- GEMM (xW+b) + per-block BN partial sums ----------------
__global__ __launch_bounds__(256) void k_gemm(const float* __restrict__ x,
                                              const float* __restrict__ W,
                                              const float* __restrict__ bias) {
    __shared__ float sW[CIN*COUT];
    __shared__ float sx[32*CIN];
    __shared__ float sred[256*8];
    int tid = threadIdx.x;

    const float4* W4 = (const float4*)W;
    float4* sW4 = (float4*)sW;
    #pragma unroll
    for (int i = 0; i < 8; i++) sW4[tid + i*256] = W4[tid + i*256];

    int c4   = (tid & 31) * 4;
    int wrow = (tid >> 5) * 4;
    float4 bv = *(const float4*)(bias + c4);

    float s0=0.f,s1=0.f,s2=0.f,s3=0.f, q0=0.f,q1=0.f,q2=0.f,q3=0.f;
    int rowblk = blockIdx.x * 128;

    for (int sub = 0; sub < 4; sub++) {
        __syncthreads();
        int r0 = rowblk + sub*32;
        const float4* xg = (const float4*)(x + (size_t)r0 * CIN);
        float4* sx4 = (float4*)sx;
        sx4[tid]       = xg[tid];
        sx4[tid + 256] = xg[tid + 256];
        __syncthreads();

        float a[4][4];
        #pragma unroll
        for (int r = 0; r < 4; r++) { a[r][0]=bv.x; a[r][1]=bv.y; a[r][2]=bv.z; a[r][3]=bv.w; }
        #pragma unroll 8
        for (int k = 0; k < CIN; k++) {
            float4 w4 = *(float4*)(sW + k*COUT + c4);
            #pragma unroll
            for (int r = 0; r < 4; r++) {
                float xv = sx[(wrow + r)*CIN + k];
                a[r][0] = fmaf(xv, w4.x, a[r][0]);
                a[r][1] = fmaf(xv, w4.y, a[r][1]);
                a[r][2] = fmaf(xv, w4.z, a[r][2]);
                a[r][3] = fmaf(xv, w4.w, a[r][3]);
            }
        }
        #pragma unroll
        for (int r = 0; r < 4; r++) {
            int row = r0 + wrow + r;
            *(float4*)(g_h + (size_t)row*COUT + c4) =
                make_float4(a[r][0], a[r][1], a[r][2], a[r][3]);
            s0 += a[r][0]; s1 += a[r][1]; s2 += a[r][2]; s3 += a[r][3];
            q0 = fmaf(a[r][0], a[r][0], q0);
            q1 = fmaf(a[r][1], a[r][1], q1);
            q2 = fmaf(a[r][2], a[r][2], q2);
            q3 = fmaf(a[r][3], a[r][3], q3);
        }
    }
    float* rp = sred + tid*8;
    rp[0]=s0; rp[1]=s1; rp[2]=s2; rp[3]=s3; rp[4]=q0; rp[5]=q1; rp[6]=q2; rp[7]=q3;
    __syncthreads();
    if (tid < 32) {
        float ss[4] = {0,0,0,0}, qq[4] = {0,0,0,0};
        for (int w = 0; w < 8; w++) {
            float* p = sred + (w*32 + tid)*8;
            #pragma unroll
            for (int i = 0; i < 4; i++) { ss[i] += p[i]; qq[i] += p[4+i]; }
        }
        #pragma unroll
        for (int i = 0; i < 4; i++) {
            int c = tid*4 + i;
            g_part[(blockIdx.x*COUT + c)*2 + 0] = ss[i];
            g_part[(blockIdx.x*COUT + c)*2 + 1] = qq[i];
        }
    }
}

// ---------------- finalize BN stats ----------------
__global__ void k_stats(const float* __restrict__ gamma, const float* __restrict__ beta) {
    int c = threadIdx.x;
    float s = 0.f, q = 0.f;
    for (int b = 0; b < NBLK_GEMM; b++) {
        s += g_part[(b*COUT + c)*2 + 0];
        q += g_part[(b*COUT + c)*2 + 1];
    }
    float mu   = s * (1.0f / BNr);
    float var  = q * (1.0f / BNr) - mu*mu;
    float rstd = rsqrtf(var + 1e-5f);
    float sc   = gamma[c] * rstd;
    g_scale[c] = sc;
    g_shift[c] = beta[c] - mu * sc;
}

// ---------------- normalize + exact GELU (in place) ----------------
__global__ __launch_bounds__(256) void k_act() {
    int i = blockIdx.x * 256 + threadIdx.x;
    float4 h = ((float4*)g_h)[i];
    int c4 = (i & 31) * 4;
    float4 sc = *(float4*)(g_scale + c4);
    float4 sh = *(float4*)(g_shift + c4);
    float y0 = fmaf(h.x, sc.x, sh.x);
    float y1 = fmaf(h.y, sc.y, sh.y);
    float y2 = fmaf(h.z, sc.z, sh.z);
    float y3 = fmaf(h.w, sc.w, sh.w);
    const float is2 = 0.70710678118654752f;
    h.x = 0.5f * y0 * (1.f + erff(y0 * is2));
    h.y = 0.5f * y1 * (1.f + erff(y1 * is2));
    h.z = 0.5f * y2 * (1.f + erff(y2 * is2));
    h.w = 0.5f * y3 * (1.f + erff(y3 * is2));
    ((float4*)g_h)[i] = h;
}

// ---------------- FPS: one block per cloud, 512 threads, 8 pts/thread ----------------
// Distances computed with the reference's exact rounding: (rn(dx^2)+rn(dy^2))+rn(dz^2),
// via packed f32x2 rn ops (no FMA contraction anywhere on this path).
__global__ __launch_bounds__(512) void k_fps(float* out_pos, float* out_batch) {
    __shared__ float4 s_last;
    __shared__ u64 s_wkey[16];
    int tid = threadIdx.x;
    int b   = blockIdx.x;
    int cb  = b * Np;
    int cbp = cb >> 1;              // pair base

    u64 npx[4], npy[4], npz[4];
    float dm[8];
    #pragma unroll
    for (int p = 0; p < 4; p++) {
        npx[p] = g_nx[cbp + tid*4 + p];
        npy[p] = g_ny[cbp + tid*4 + p];
        npz[p] = g_nz[cbp + tid*4 + p];
    }
    #pragma unroll
    for (int j = 0; j < 8; j++) dm[j] = CUDART_INF_F;

    if (tid == 0) {
        float4 p = g_pos4[cb];
        s_last = p;
        int q = b * Ms;
        g_qpos[q] = p;
        if (out_pos) {
            out_pos[(size_t)q*3+0] = p.x; out_pos[(size_t)q*3+1] = p.y; out_pos[(size_t)q*3+2] = p.z;
            out_batch[q] = (float)b;
        }
    }
    __syncthreads();

    int lane = tid & 31, w = tid >> 5;
    for (int m = 1; m < Ms; m++) {
        float4 a = s_last;
        u64 ax = packx2(a.x, a.x);
        u64 ay = packx2(a.y, a.y);
        u64 az = packx2(a.z, a.z);
        float mm = -1.0f;
        #pragma unroll
        for (int p = 0; p < 4; p++) {
            u64 dx, dy, dz, s2x, s2y, s2z, s;
            ADDX2(dx, ax, npx[p]);           // rn(a-p)  (sign-flipped vs ref; square equal)
            ADDX2(dy, ay, npy[p]);
            ADDX2(dz, az, npz[p]);
            MULX2(s2x, dx, dx);
            MULX2(s2y, dy, dy);
            MULX2(s2z, dz, dz);
            ADDX2(s, s2x, s2y);
            ADDX2(s, s, s2z);
            float lo, hi; unpackx2(lo, hi, s);
            dm[2*p]   = fminf(dm[2*p],   lo);
            dm[2*p+1] = fminf(dm[2*p+1], hi);
            mm = fmaxf(mm, fmaxf(dm[2*p], dm[2*p+1]));
        }
        unsigned u    = __float_as_uint(mm);         // all dm >= 0 after first update
        unsigned wmax = __reduce_max_sync(0xFFFFFFFFu, u);
        unsigned eqm  = __ballot_sync(0xFFFFFFFFu, u == wmax);
        int src = __ffs(eqm) - 1;
        int myidx = 0;
        if (u == wmax) {
            int jb = 7;
            #pragma unroll
            for (int j = 6; j >= 0; j--) if (dm[j] == mm) jb = j;   // lowest index on tie
            myidx = tid*8 + jb;
        }
        int widx = __shfl_sync(0xFFFFFFFFu, myidx, src);
        if (lane == 0) s_wkey[w] = ((u64)wmax << 32) | (unsigned)widx;
        __syncthreads();
        if (tid < 16) {
            u64 kk = s_wkey[tid];
            unsigned hi   = (unsigned)(kk >> 32);
            unsigned bmax = __reduce_max_sync(0xFFFFu, hi);
            unsigned em   = __ballot_sync(0xFFFFu, hi == bmax);
            int s2        = __ffs(em) - 1;
            unsigned lo   = __shfl_sync(0xFFFFu, (unsigned)kk, s2);
            if (tid == 0) {
                int idx  = (int)lo;
                float4 p = g_pos4[cb + idx];
                s_last = p;
                int q = b * Ms + m;
                g_qpos[q] = p;
                if (out_pos) {
                    out_pos[(size_t)q*3+0] = p.x; out_pos[(size_t)q*3+1] = p.y; out_pos[(size_t)q*3+2] = p.z;
                    out_batch[q] = (float)b;
                }
            }
        }
        __syncthreads();
    }
}

// ---------------- KNN: thread per query, exact distances, top-16 in registers ----------------
__global__ __launch_bounds__(256) void k_knn() {
    int tid = threadIdx.x;
    int bid = blockIdx.x;
    int b   = bid >> 3;
    int cb  = b * Np;
    int cbp = cb >> 1;
    int q   = b * Ms + (bid & 7) * 256 + tid;

    float4 qp = g_qpos[q];
    u64 qx = packx2(qp.x, qp.x);
    u64 qy = packx2(qp.y, qp.y);
    u64 qz = packx2(qp.z, qp.z);

    float dd[16]; int ii[16];
    #pragma unroll
    for (int k = 0; k < 16; k++) { dd[k] = CUDART_INF_F; ii[k] = 0; }
    float thr = CUDART_INF_F; int mp = 0;

    // keep-16-smallest, ties prefer lowest index:
    //  - insert only if strictly smaller than current worst
    //  - evict the highest-indexed element among those tied at the worst value
    auto ins = [&](float t, int idxv) {
        if (t < thr) {
            dd[mp] = t; ii[mp] = idxv;
            thr = dd[0]; mp = 0;
            #pragma unroll
            for (int k = 1; k < 16; k++)
                if (dd[k] > thr || (dd[k] == thr && ii[k] > ii[mp])) { thr = dd[k]; mp = k; }
        }
    };

    #pragma unroll 4
    for (int j = 0; j < Np/2; j++) {
        u64 dx, dy, dz, s2x, s2y, s2z, s;
        ADDX2(dx, qx, g_nx[cbp + j]);      // rn(q-p)
        ADDX2(dy, qy, g_ny[cbp + j]);
        ADDX2(dz, qz, g_nz[cbp + j]);
        MULX2(s2x, dx, dx);
        MULX2(s2y, dy, dy);
        MULX2(s2z, dz, dz);
        ADDX2(s, s2x, s2y);
        ADDX2(s, s, s2z);
        float lo, hi; unpackx2(lo, hi, s);
        ins(lo, 2*j);
        ins(hi, 2*j + 1);
    }
    #pragma unroll
    for (int k = 0; k < 16; k++) g_nbr[(size_t)q*Kn + k] = cb + ii[k];
}

// ---------------- gather + max-pool: warp per query ----------------
__global__ __launch_bounds__(256) void k_gather(float* __restrict__ out_x) {
    int gq   = (blockIdx.x * 256 + threadIdx.x) >> 5;
    int lane = threadIdx.x & 31;
    int nb[16];
    #pragma unroll
    for (int k = 0; k < 16; k++) nb[k] = g_nbr[(size_t)gq*Kn + k];
    float4 acc = make_float4(-CUDART_INF_F, -CUDART_INF_F, -CUDART_INF_F, -CUDART_INF_F);
    #pragma unroll
    for (int k = 0; k < 16; k++) {
        float4 v = *(const float4*)(g_h + (size_t)nb[k]*COUT + lane*4);
        acc.x = fmaxf(acc.x, v.x);
        acc.y = fmaxf(acc.y, v.y);
        acc.z = fmaxf(acc.z, v.z);
        acc.w = fmaxf(acc.w, v.w);
    }
    *(float4*)(out_x + (size_t)gq*COUT + lane*4) = acc;
}

// ---------------- launch ----------------
extern "C" void kernel_launch(void* const* d_in, const int* in_sizes, int n_in,
                              void* d_out, int out_size) {
    const float* x     = (const float*)d_in[0];
    const float* pos   = (const float*)d_in[1];
    const float* W     = (const float*)d_in[3];
    const float* bias  = (const float*)d_in[4];
    const float* gamma = (const float*)d_in[5];
    const float* beta  = (const float*)d_in[6];

    float* out       = (float*)d_out;
    float* out_x     = out;
    float* out_pos   = nullptr;
    float* out_batch = nullptr;
    if (out_size >= BM*COUT + BM*3 + BM) {
        out_pos   = out + BM*COUT;
        out_batch = out + BM*COUT + BM*3;
    }

    k_prep  <<<(BNr/2 + 255)/256, 256>>>(pos);
    k_fps   <<<Bc, 512>>>(out_pos, out_batch);
    k_gemm  <<<NBLK_GEMM, 256>>>(x, W, bias);
    k_stats <<<1, COUT>>>(gamma, beta);
    k_act   <<<(BNr*COUT/4)/256, 256>>>();
    k_knn   <<<Bc*8, 256>>>();
    k_gather<<<BM/8, 256>>>(out_x);
}

// round 4
// speedup vs baseline: 1.7748x; 1.7748x over previous
#include <cuda_runtime.h>
#include <math_constants.h>
#include <cstdint>

#define Bc    8
#define Np    4096
#define Ms    2048
#define Kn    16
#define CIN   64
#define COUT  128
#define BNr   (Bc*Np)     // 32768
#define BM    (Bc*Ms)     // 16384
#define NBLK_GEMM 256

typedef unsigned long long u64;
typedef unsigned int u32;

// packed f32x2 ops: each half is IEEE rn => bit-identical to scalar rn ops
#define ADDX2(o,a,b) asm("add.rn.f32x2 %0,%1,%2;" : "=l"(o) : "l"(a), "l"(b))
#define MULX2(o,a,b) asm("mul.rn.f32x2 %0,%1,%2;" : "=l"(o) : "l"(a), "l"(b))
__device__ __forceinline__ u64 packx2(float lo, float hi) {
    u64 o; asm("mov.b64 %0,{%1,%2};" : "=l"(o) : "f"(lo), "f"(hi)); return o;
}
__device__ __forceinline__ void unpackx2(float& lo, float& hi, u64 v) {
    asm("mov.b64 {%0,%1},%2;" : "=f"(lo), "=f"(hi) : "l"(v));
}

// ---------------- device scratch ----------------
__device__ float  g_h[BNr*COUT];             // mlp activations
__device__ float  g_part[NBLK_GEMM*COUT*2];
__device__ float  g_scale[COUT];
__device__ float  g_shift[COUT];
__device__ float4 g_pos4[BNr];               // original order xyz
__device__ float4 g_spos4[BNr];              // Morton-sorted xyz, w = orig local idx bits
__device__ u64    g_nx[BNr/2];               // sorted, packed (-x) pairs
__device__ u64    g_ny[BNr/2];
__device__ u64    g_nz[BNr/2];
__device__ u64    g_oi2[BNr/2];              // sorted, two orig local indices
__device__ float4 g_qpos[BM];                // sampled points
__device__ u64    g_kpart[BM*4*16];          // per-segment top-16 keys
__device__ int    g_nbr[BM*Kn];

// ---------------- prep ----------------
__global__ __launch_bounds__(256) void k_prep(const float* __restrict__ pos) {
    int i = blockIdx.x * 256 + threadIdx.x;
    if (i >= BNr) return;
    const float* pp = pos + (size_t)i * 3;
    g_pos4[i] = make_float4(pp[0], pp[1], pp[2], 0.f);
}

// ---------------- per-cloud Morton counting sort ----------------
__device__ __forceinline__ u32 mort3(u32 v) { return (v & 1u) | ((v & 2u) << 2) | ((v & 4u) << 4); }

__global__ __launch_bounds__(512) void k_sort() {
    __shared__ u32 hist[512];
    __shared__ u32 wsum[16];
    int tid = threadIdx.x, b = blockIdx.x, cb = b * Np;
    hist[tid] = 0;
    __syncthreads();
    float4 pt[8]; u32 code[8];
    #pragma unroll
    for (int j = 0; j < 8; j++) {
        int li = j * 512 + tid;
        float4 p = g_pos4[cb + li];
        int cx = min(7, max(0, (int)(p.x * 8.f)));
        int cy = min(7, max(0, (int)(p.y * 8.f)));
        int cz = min(7, max(0, (int)(p.z * 8.f)));
        code[j] = (mort3(cx) << 2) | (mort3(cy) << 1) | mort3(cz);
        p.w = __uint_as_float((u32)li);
        pt[j] = p;
        atomicAdd(&hist[code[j]], 1u);
    }
    __syncthreads();
    u32 v = hist[tid];
    u32 inc = v;
    #pragma unroll
    for (int o = 1; o < 32; o <<= 1) {
        u32 t = __shfl_up_sync(0xFFFFFFFFu, inc, o);
        if ((tid & 31) >= o) inc += t;
    }
    if ((tid & 31) == 31) wsum[tid >> 5] = inc;
    __syncthreads();
    if (tid < 32) {
        u32 s = (tid < 16) ? wsum[tid] : 0u;
        u32 in2 = s;
        #pragma unroll
        for (int o = 1; o < 16; o <<= 1) {
            u32 t = __shfl_up_sync(0xFFFFFFFFu, in2, o);
            if (tid >= o) in2 += t;
        }
        if (tid < 16) wsum[tid] = in2 - s;
    }
    __syncthreads();
    hist[tid] = inc - v + wsum[tid >> 5];
    __syncthreads();
    #pragma unroll
    for (int j = 0; j < 8; j++) {
        u32 dst = atomicAdd(&hist[code[j]], 1u);
        g_spos4[cb + dst] = pt[j];
    }
}

// ---------------- pack sorted pairs for KNN ----------------
__global__ __launch_bounds__(256) void k_pack() {
    int i = blockIdx.x * 256 + threadIdx.x;   // pair index
    if (i >= BNr/2) return;
    float4 p0 = g_spos4[2*i], p1 = g_spos4[2*i+1];
    g_nx[i] = packx2(-p0.x, -p1.x);
    g_ny[i] = packx2(-p0.y, -p1.y);
    g_nz[i] = packx2(-p0.z, -p1.z);
    g_oi2[i] = ((u64)__float_as_uint(p1.w) << 32) | __float_as_uint(p0.w);
}

// ---------------- GEMM + BN partials ----------------
__global__ __launch_bounds__(256) void k_gemm(const float* __restrict__ x,
                                              const float* __restrict__ W,
                                              const float* __restrict__ bias) {
    __shared__ float sW[CIN*COUT];
    __shared__ float sx[32*CIN];
    __shared__ float sred[256*8];
    int tid = threadIdx.x;

    const float4* W4 = (const float4*)W;
    float4* sW4 = (float4*)sW;
    #pragma unroll
    for (int i = 0; i < 8; i++) sW4[tid + i*256] = W4[tid + i*256];

    int c4   = (tid & 31) * 4;
    int wrow = (tid >> 5) * 4;
    float4 bv = *(const float4*)(bias + c4);

    float s0=0.f,s1=0.f,s2=0.f,s3=0.f, q0=0.f,q1=0.f,q2=0.f,q3=0.f;
    int rowblk = blockIdx.x * 128;

    for (int sub = 0; sub < 4; sub++) {
        __syncthreads();
        int r0 = rowblk + sub*32;
        const float4* xg = (const float4*)(x + (size_t)r0 * CIN);
        float4* sx4 = (float4*)sx;
        sx4[tid]       = xg[tid];
        sx4[tid + 256] = xg[tid + 256];
        __syncthreads();

        float a[4][4];
        #pragma unroll
        for (int r = 0; r < 4; r++) { a[r][0]=bv.x; a[r][1]=bv.y; a[r][2]=bv.z; a[r][3]=bv.w; }
        #pragma unroll 8
        for (int k = 0; k < CIN; k++) {
            float4 w4 = *(float4*)(sW + k*COUT + c4);
            #pragma unroll
            for (int r = 0; r < 4; r++) {
                float xv = sx[(wrow + r)*CIN + k];
                a[r][0] = fmaf(xv, w4.x, a[r][0]);
                a[r][1] = fmaf(xv, w4.y, a[r][1]);
                a[r][2] = fmaf(xv, w4.z, a[r][2]);
                a[r][3] = fmaf(xv, w4.w, a[r][3]);
            }
        }
        #pragma unroll
        for (int r = 0; r < 4; r++) {
            int row = r0 + wrow + r;
            *(float4*)(g_h + (size_t)row*COUT + c4) =
                make_float4(a[r][0], a[r][1], a[r][2], a[r][3]);
            s0 += a[r][0]; s1 += a[r][1]; s2 += a[r][2]; s3 += a[r][3];
            q0 = fmaf(a[r][0], a[r][0], q0);
            q1 = fmaf(a[r][1], a[r][1], q1);
            q2 = fmaf(a[r][2], a[r][2], q2);
            q3 = fmaf(a[r][3], a[r][3], q3);
        }
    }
    float* rp = sred + tid*8;
    rp[0]=s0; rp[1]=s1; rp[2]=s2; rp[3]=s3; rp[4]=q0; rp[5]=q1; rp[6]=q2; rp[7]=q3;
    __syncthreads();
    if (tid < 32) {
        float ss[4] = {0,0,0,0}, qq[4] = {0,0,0,0};
        for (int w = 0; w < 8; w++) {
            float* p = sred + (w*32 + tid)*8;
            #pragma unroll
            for (int i = 0; i < 4; i++) { ss[i] += p[i]; qq[i] += p[4+i]; }
        }
        #pragma unroll
        for (int i = 0; i < 4; i++) {
            int c = tid*4 + i;
            g_part[(blockIdx.x*COUT + c)*2 + 0] = ss[i];
            g_part[(blockIdx.x*COUT + c)*2 + 1] = qq[i];
        }
    }
}

__global__ void k_stats(const float* __restrict__ gamma, const float* __restrict__ beta) {
    int c = threadIdx.x;
    float s = 0.f, q = 0.f;
    for (int b = 0; b < NBLK_GEMM; b++) {
        s += g_part[(b*COUT + c)*2 + 0];
        q += g_part[(b*COUT + c)*2 + 1];
    }
    float mu   = s * (1.0f / BNr);
    float var  = q * (1.0f / BNr) - mu*mu;
    float rstd = rsqrtf(var + 1e-5f);
    float sc   = gamma[c] * rstd;
    g_scale[c] = sc;
    g_shift[c] = beta[c] - mu * sc;
}

__global__ __launch_bounds__(256) void k_act() {
    int i = blockIdx.x * 256 + threadIdx.x;
    float4 h = ((float4*)g_h)[i];
    int c4 = (i & 31) * 4;
    float4 sc = *(float4*)(g_scale + c4);
    float4 sh = *(float4*)(g_shift + c4);
    float y0 = fmaf(h.x, sc.x, sh.x);
    float y1 = fmaf(h.y, sc.y, sh.y);
    float y2 = fmaf(h.z, sc.z, sh.z);
    float y3 = fmaf(h.w, sc.w, sh.w);
    const float is2 = 0.70710678118654752f;
    h.x = 0.5f * y0 * (1.f + erff(y0 * is2));
    h.y = 0.5f * y1 * (1.f + erff(y1 * is2));
    h.z = 0.5f * y2 * (1.f + erff(y2 * is2));
    h.w = 0.5f * y3 * (1.f + erff(y3 * is2));
    ((float4*)g_h)[i] = h;
}

// ---------------- pruned FPS over Morton-sorted points ----------------
// Skip rule (exact-safe): if lower-bound dist(a, group bbox)^2 * 0.999 >= group max dmin,
// no dmin in the group can change; contribute cached max. Ties broken on orig index.
__global__ __launch_bounds__(512) void k_fps(float* out_pos, float* out_batch) {
    __shared__ u64 s_wkey[2][16];
    int tid = threadIdx.x, b = blockIdx.x, cb = b * Np;
    int lane = tid & 31, w = tid >> 5;

    float dm[8]; u32 oi[8];
    u64 npx[4], npy[4], npz[4];
    float lox =  CUDART_INF_F, loy =  CUDART_INF_F, loz =  CUDART_INF_F;
    float hix = -CUDART_INF_F, hiy = -CUDART_INF_F, hiz = -CUDART_INF_F;
    {
        float tx[8], ty[8], tz[8];
        #pragma unroll
        for (int j = 0; j < 8; j++) {
            float4 p = g_spos4[cb + tid*8 + j];
            tx[j] = p.x; ty[j] = p.y; tz[j] = p.z;
            oi[j] = __float_as_uint(p.w);
            dm[j] = CUDART_INF_F;
            lox = fminf(lox, p.x); hix = fmaxf(hix, p.x);
            loy = fminf(loy, p.y); hiy = fmaxf(hiy, p.y);
            loz = fminf(loz, p.z); hiz = fmaxf(hiz, p.z);
        }
        #pragma unroll
        for (int p = 0; p < 4; p++) {
            npx[p] = packx2(-tx[2*p], -tx[2*p+1]);
            npy[p] = packx2(-ty[2*p], -ty[2*p+1]);
            npz[p] = packx2(-tz[2*p], -tz[2*p+1]);
        }
    }
    float gmaxd = CUDART_INF_F; u32 gidx = 0;

    float4 a4 = g_pos4[cb];          // first sample = orig index 0
    float ax = a4.x, ay = a4.y, az = a4.z;
    if (tid == 0) {
        int q = b * Ms;
        g_qpos[q] = a4;
        if (out_pos) {
            out_pos[(size_t)q*3+0] = a4.x; out_pos[(size_t)q*3+1] = a4.y; out_pos[(size_t)q*3+2] = a4.z;
            out_batch[q] = (float)b;
        }
    }

    for (int m = 1; m < Ms; m++) {
        // conservative lower bound to bbox
        float bx = fmaxf(fmaxf(lox - ax, ax - hix), 0.f);
        float by = fmaxf(fmaxf(loy - ay, ay - hiy), 0.f);
        float bz = fmaxf(fmaxf(loz - az, az - hiz), 0.f);
        float LB = (bx*bx + by*by + bz*bz) * 0.999f;
        if (LB < gmaxd) {
            u64 pax = packx2(ax, ax), pay = packx2(ay, ay), paz = packx2(az, az);
            #pragma unroll
            for (int p = 0; p < 4; p++) {
                u64 dx, dy, dz, s2x, s2y, s2z, s;
                ADDX2(dx, pax, npx[p]);
                ADDX2(dy, pay, npy[p]);
                ADDX2(dz, paz, npz[p]);
                MULX2(s2x, dx, dx);
                MULX2(s2y, dy, dy);
                MULX2(s2z, dz, dz);
                ADDX2(s, s2x, s2y);
                ADDX2(s, s, s2z);
                float lo, hi; unpackx2(lo, hi, s);
                dm[2*p]   = fminf(dm[2*p],   lo);
                dm[2*p+1] = fminf(dm[2*p+1], hi);
            }
            gmaxd = dm[0]; gidx = ((4095u - oi[0]) << 12) | (u32)(tid*8);
            #pragma unroll
            for (int j = 1; j < 8; j++) {
                u32 ij = ((4095u - oi[j]) << 12) | (u32)(tid*8 + j);
                if (dm[j] > gmaxd || (dm[j] == gmaxd && ij > gidx)) { gmaxd = dm[j]; gidx = ij; }
            }
        }
        // stage 1: warp reduce (d, idx)
        u32 db = __float_as_uint(gmaxd);
        u32 bd = __reduce_max_sync(0xFFFFFFFFu, db);
        u32 c  = (db == bd) ? gidx : 0u;
        u32 bi = __reduce_max_sync(0xFFFFFFFFu, c);
        if (lane == 0) s_wkey[m & 1][w] = ((u64)bd << 32) | bi;
        __syncthreads();
        // stage 2: every warp redundantly reduces the 16 warp keys
        u64 kk  = s_wkey[m & 1][lane & 15];
        u32 hb  = (u32)(kk >> 32);
        u32 bd2 = __reduce_max_sync(0xFFFFFFFFu, hb);
        u32 c2  = (hb == bd2) ? (u32)kk : 0u;
        u32 wi  = __reduce_max_sync(0xFFFFFFFFu, c2);
        int spos = (int)(wi & 0xFFFu);
        float4 p = g_spos4[cb + spos];    // uniform broadcast load (L1)
        ax = p.x; ay = p.y; az = p.z;
        if (tid == 0) {
            int q = b * Ms + m;
            g_qpos[q] = p;
            if (out_pos) {
                out_pos[(size_t)q*3+0] = p.x; out_pos[(size_t)q*3+1] = p.y; out_pos[(size_t)q*3+2] = p.z;
                out_batch[q] = (float)b;
            }
        }
    }
}

// ---------------- segmented KNN: 4 segments x 1024 sorted points ----------------
__global__ __launch_bounds__(256) void k_knn() {
    int tid = threadIdx.x, bid = blockIdx.x;
    int b  = bid >> 5;            // cloud
    int s  = (bid >> 3) & 3;      // segment
    int qb = bid & 7;             // query block
    int q  = b * Ms + qb * 256 + tid;
    int base = b * (Np/2) + s * 512;   // pair base

    float4 qp = g_qpos[q];
    u64 qx = packx2(qp.x, qp.x);
    u64 qy = packx2(qp.y, qp.y);
    u64 qz = packx2(qp.z, qp.z);

    u64 dd[16];
    #pragma unroll
    for (int k = 0; k < 16; k++) dd[k] = ~0ull;
    u64 kmax = ~0ull; int mp = 0;

    auto ins = [&](u64 key) {
        if (key < kmax) {
            dd[mp] = key;
            kmax = dd[0]; mp = 0;
            #pragma unroll
            for (int k = 1; k < 16; k++) if (dd[k] > kmax) { kmax = dd[k]; mp = k; }
        }
    };

    #pragma unroll 4
    for (int j = 0; j < 512; j++) {
        u64 ox = g_nx[base + j], oy = g_ny[base + j], oz = g_nz[base + j];
        u64 oo = g_oi2[base + j];
        u64 dx, dy, dz, s2x, s2y, s2z, sum;
        ADDX2(dx, qx, ox);
        ADDX2(dy, qy, oy);
        ADDX2(dz, qz, oz);
        MULX2(s2x, dx, dx);
        MULX2(s2y, dy, dy);
        MULX2(s2z, dz, dz);
        ADDX2(sum, s2x, s2y);
        ADDX2(sum, sum, s2z);
        float lo, hi; unpackx2(lo, hi, sum);
        ins(((u64)__float_as_uint(lo) << 32) | (u32)oo);
        ins(((u64)__float_as_uint(hi) << 32) | (u32)(oo >> 32));
    }
    u64* dst = g_kpart + ((size_t)q * 4 + s) * 16;
    #pragma unroll
    for (int k = 0; k < 16; k++) dst[k] = dd[k];
}

// ---------------- merge 4 segment lists -> exact global top-16 ----------------
__global__ __launch_bounds__(256) void k_merge() {
    int q = blockIdx.x * 256 + threadIdx.x;
    const u64* src = g_kpart + (size_t)q * 64;
    u64 best[16];
    #pragma unroll
    for (int k = 0; k < 16; k++) best[k] = src[k];
    u64 kmax = best[0]; int mp = 0;
    #pragma unroll
    for (int k = 1; k < 16; k++) if (best[k] > kmax) { kmax = best[k]; mp = k; }
    for (int t = 16; t < 64; t++) {
        u64 v = src[t];
        if (v < kmax) {
            best[mp] = v;
            kmax = best[0]; mp = 0;
            #pragma unroll
            for (int k = 1; k < 16; k++) if (best[k] > kmax) { kmax = best[k]; mp = k; }
        }
    }
    int cb = (q >> 11) * Np;
    #pragma unroll
    for (int k = 0; k < 16; k++)
        g_nbr[(size_t)q*Kn + k] = cb + (int)(best[k] & 0xFFFFFFFFu);
}

// ---------------- gather + max-pool ----------------
__global__ __launch_bounds__(256) void k_gather(float* __restrict__ out_x) {
    int gq   = (blockIdx.x * 256 + threadIdx.x) >> 5;
    int lane = threadIdx.x & 31;
    int nb[16];
    #pragma unroll
    for (int k = 0; k < 16; k++) nb[k] = g_nbr[(size_t)gq*Kn + k];
    float4 acc = make_float4(-CUDART_INF_F, -CUDART_INF_F, -CUDART_INF_F, -CUDART_INF_F);
    #pragma unroll
    for (int k = 0; k < 16; k++) {
        float4 v = *(const float4*)(g_h + (size_t)nb[k]*COUT + lane*4);
        acc.x = fmaxf(acc.x, v.x);
        acc.y = fmaxf(acc.y, v.y);
        acc.z = fmaxf(acc.z, v.z);
        acc.w = fmaxf(acc.w, v.w);
    }
    *(float4*)(out_x + (size_t)gq*COUT + lane*4) = acc;
}

// ---------------- launch ----------------
extern "C" void kernel_launch(void* const* d_in, const int* in_sizes, int n_in,
                              void* d_out, int out_size) {
    const float* x     = (const float*)d_in[0];
    const float* pos   = (const float*)d_in[1];
    const float* W     = (const float*)d_in[3];
    const float* bias  = (const float*)d_in[4];
    const float* gamma = (const float*)d_in[5];
    const float* beta  = (const float*)d_in[6];

    float* out       = (float*)d_out;
    float* out_x     = out;
    float* out_pos   = nullptr;
    float* out_batch = nullptr;
    if (out_size >= BM*COUT + BM*3 + BM) {
        out_pos   = out + BM*COUT;
        out_batch = out + BM*COUT + BM*3;
    }

    k_prep  <<<(BNr + 255)/256, 256>>>(pos);
    k_sort  <<<Bc, 512>>>();
    k_pack  <<<(BNr/2 + 255)/256, 256>>>();
    k_fps   <<<Bc, 512>>>(out_pos, out_batch);
    k_gemm  <<<NBLK_GEMM, 256>>>(x, W, bias);
    k_stats <<<1, COUT>>>(gamma, beta);
    k_act   <<<(BNr*COUT/4)/256, 256>>>();
    k_knn   <<<Bc*32, 256>>>();
    k_merge <<<BM/256, 256>>>();
    k_gather<<<BM/8, 256>>>(out_x);
}